// round 12
// baseline (speedup 1.0000x reference)
#include <cuda_runtime.h>
#include <cstddef>
#include <cstdint>

#define NB 64
#define NT 1024
#define NV 256
#define NS 256
#define ND 24
#define NL 513          // 2*NS+1
#define DGA 1344        // allocated dg rows per batch
#define EMW 260         // em row: [0..255]=labels, [256]=blank, pad to 260
#define KPH 16          // steps per phase
#define MLAG_S 3        // sdtw inter-warp lag (phases): (m-1)*16 >= 31 -> m=3
#define NPH_S 87        // sdtw phases: 66 active + 3*7 lag
#define NPH_C 71        // ctc phases: 64 active + 7 lag
#define STROW 36        // staged row: 32 data floats (+blank at [32] for ctc), padded
#define STQ (3 * KPH * STROW)   // per-warp stage floats (3 buffers) = 1728
#define GAMMA 0.1f
#define NEGF (-1e10f)
#define BIGF (1e10f)

// Scratch (no allocation allowed)
__device__ float g_pred[NB * NT * ND];            // predicted features (B,T,D)
__device__ float g_cost[(size_t)NB * DGA * NS];   // cost, [b][dg][j], dg=i+j+2
__device__ float g_em[(size_t)NB * NT * EMW];     // emissions per label + blank
__device__ float g_loss[2 * NB];                  // [0..63] ctc, [64..127] sdtw

// mn <= md <= mx with pure min/max (no cancellation)
__device__ __forceinline__ void sort3(float a, float b, float c,
                                      float& mn, float& md, float& mx) {
    float t1 = fminf(a, b);
    float t2 = fmaxf(a, b);
    mn = fminf(t1, c);
    mx = fmaxf(t2, c);
    md = fmaxf(t1, fminf(t2, c));
}

__device__ __forceinline__ void cpAsync16(uint32_t dst, const void* src) {
    asm volatile("cp.async.cg.shared.global [%0], [%1], 16;" :: "r"(dst), "l"(src));
}
__device__ __forceinline__ void cpAsync4(uint32_t dst, const void* src) {
    asm volatile("cp.async.ca.shared.global [%0], [%1], 4;" :: "r"(dst), "l"(src));
}
__device__ __forceinline__ void cpCommit() {
    asm volatile("cp.async.commit_group;" ::: "memory");
}
__device__ __forceinline__ void cpWait2() {
    asm volatile("cp.async.wait_group 2;" ::: "memory");
}
// named block barrier over 256 threads (group-scoped; decouples the 2 pipelines)
__device__ __forceinline__ void barNamed(int id) {
    asm volatile("bar.sync %0, 256;" :: "r"(id) : "memory");
}

// ----------------------------------------------------------------------------
// Kernel 1: pred = exp(log_probs) @ fm   (65536 x 256) @ (256 x 24)
// ----------------------------------------------------------------------------
__global__ __launch_bounds__(256) void prep_kernel(const float* __restrict__ lp,
                                                   const float* __restrict__ fm) {
    __shared__ float eS[64 * 129];
    __shared__ float fmS[64 * 25];

    const int tid = threadIdx.x;
    const int row0 = blockIdx.x * 128;
    const int rg = tid >> 3;
    const int dgrp = tid & 7;

    float acc[4][3];
#pragma unroll
    for (int i = 0; i < 4; i++)
#pragma unroll
        for (int j = 0; j < 3; j++) acc[i][j] = 0.f;

    for (int v0 = 0; v0 < NV; v0 += 64) {
        for (int idx = tid; idx < 64 * 24; idx += 256) {
            int v = idx / 24, d = idx - v * 24;
            fmS[v * 25 + d] = fm[(v0 + v) * ND + d];
        }
        for (int idx = tid; idx < 128 * 64; idx += 256) {
            int r = idx >> 6, v = idx & 63;
            eS[v * 129 + r] = __expf(lp[(size_t)(row0 + r) * NV + v0 + v]);
        }
        __syncthreads();

#pragma unroll 4
        for (int v = 0; v < 64; v++) {
            float e0 = eS[v * 129 + rg * 4 + 0];
            float e1 = eS[v * 129 + rg * 4 + 1];
            float e2 = eS[v * 129 + rg * 4 + 2];
            float e3 = eS[v * 129 + rg * 4 + 3];
            float f0 = fmS[v * 25 + dgrp * 3 + 0];
            float f1 = fmS[v * 25 + dgrp * 3 + 1];
            float f2 = fmS[v * 25 + dgrp * 3 + 2];
            acc[0][0] += e0 * f0; acc[0][1] += e0 * f1; acc[0][2] += e0 * f2;
            acc[1][0] += e1 * f0; acc[1][1] += e1 * f1; acc[1][2] += e1 * f2;
            acc[2][0] += e2 * f0; acc[2][1] += e2 * f1; acc[2][2] += e2 * f2;
            acc[3][0] += e3 * f0; acc[3][1] += e3 * f1; acc[3][2] += e3 * f2;
        }
        __syncthreads();
    }

#pragma unroll
    for (int i = 0; i < 4; i++)
#pragma unroll
        for (int j = 0; j < 3; j++)
            g_pred[(size_t)(row0 + rg * 4 + i) * ND + dgrp * 3 + j] = acc[i][j];
}

// ----------------------------------------------------------------------------
// Kernel 2: sdtw cost matrix, layout [b][dg][j], coalesced via diagonal rotation.
// ----------------------------------------------------------------------------
__global__ __launch_bounds__(256) void cost_kernel(const float* __restrict__ fm,
                                                   const int* __restrict__ targets) {
    __shared__ float predS[64 * 25];
    __shared__ float qS[256 * 25];
    __shared__ float pn[64];
    __shared__ float qn[256];
    __shared__ int qlab[256];

    const int tid = threadIdx.x;
    const int b = blockIdx.y;
    const int i0 = blockIdx.x * 64;

    qlab[tid] = targets[b * NS + tid];
    for (int idx = tid; idx < 64 * 24; idx += 256)
        predS[(idx / 24) * 25 + (idx % 24)] = g_pred[(size_t)(b * NT + i0) * ND + idx];
    __syncthreads();
    for (int idx = tid; idx < 256 * 24; idx += 256) {
        int c = idx / 24, d = idx - c * 24;
        qS[c * 25 + d] = fm[qlab[c] * ND + d];
    }
    __syncthreads();
    if (tid < 64) {
        float s = 0.f;
#pragma unroll
        for (int d = 0; d < ND; d++) { float x = predS[tid * 25 + d]; s += x * x; }
        pn[tid] = s;
    }
    {
        float s = 0.f;
#pragma unroll
        for (int d = 0; d < ND; d++) { float x = qS[tid * 25 + d]; s += x * x; }
        qn[tid] = s;
    }
    __syncthreads();

    const int w = tid >> 5;
    const int lane = tid & 31;
    const int j0 = w * 32;

    float p0[ND], p1[ND];
#pragma unroll
    for (int k = 0; k < ND; k++) {
        p0[k] = predS[lane * 25 + k];
        p1[k] = predS[(lane + 32) * 25 + k];
    }
    const float pn0 = pn[lane], pn1 = pn[lane + 32];
    const size_t cb = (size_t)b * DGA;
    const int D0 = i0 + j0 + 2;

#pragma unroll 4
    for (int c = 0; c < 32; c++) {
        int jc = j0 + ((c - lane) & 31);
        float dot0 = 0.f, dot1 = 0.f;
#pragma unroll
        for (int k = 0; k < ND; k++) {
            float q = qS[jc * 25 + k];
            dot0 += p0[k] * q;
            dot1 += p1[k] * q;
        }
        float qnj = qn[jc];
        int dg0 = D0 + c + ((lane > c) ? 32 : 0);
        g_cost[(cb + dg0) * NS + jc] = pn0 + qnj - 2.f * dot0;
        g_cost[(cb + dg0 + 32) * NS + jc] = pn1 + qnj - 2.f * dot1;
    }
}

// ----------------------------------------------------------------------------
// Kernel 3: emission table em[b][t][j] = lp[t][tgt[j]] (j<256); [256] = blank.
// ----------------------------------------------------------------------------
__global__ __launch_bounds__(256) void em_kernel(const float* __restrict__ lp,
                                                 const int* __restrict__ targets) {
    __shared__ float rowS[4][256];
    __shared__ int tgtS[256];

    const int tid = threadIdx.x;
    const int b = blockIdx.x >> 4;
    const int t0 = (blockIdx.x & 15) << 6;

    tgtS[tid] = targets[b * NS + tid];
    const float* lpb = lp + ((size_t)b * NT + t0) * NV;
    float* emb = g_em + ((size_t)b * NT + t0) * EMW;
    __syncthreads();

    for (int tt = 0; tt < 64; tt += 4) {
#pragma unroll
        for (int r = 0; r < 4; r++)
            rowS[r][tid] = lpb[(size_t)(tt + r) * NV + tid];
        __syncthreads();
#pragma unroll
        for (int r = 0; r < 4; r++)
            emb[(size_t)(tt + r) * EMW + tid] = rowS[r][tgtS[tid]];
        if (tid < 4) emb[(size_t)(tt + tid) * EMW + 256] = rowS[tid][0];
        __syncthreads();
    }
}

// ----------------------------------------------------------------------------
// Kernel 4 (fused DP, both pipelines in ONE block per batch, 16 warps =
// 4 independent chains per SMSP; named barriers decouple the pipelines):
//   warps 0..7  -> soft-DTW : 1 col/thread, lag m=3 (bar.sync 1)
//   warps 8..15 -> CTC      : 2 states/thread, lag m=1 (bar.sync 2)
// cp.async per-warp staging; phase-skewed barriers.
// ----------------------------------------------------------------------------
extern __shared__ float smf[];

__global__ __launch_bounds__(512) void main_kernel(const int* __restrict__ targets,
                                                   const int* __restrict__ in_len,
                                                   const int* __restrict__ tg_len) {
    float* stage = smf;                                  // [16][STQ]
    float* bndR = smf + 16 * STQ;                        // [8][1312]
    float* ringT = bndR + 8 * 1312;                      // [8][64]
    float* actc = ringT + 8 * 64;                        // [513]

    const int tid = threadIdx.x;                         // 0..511
    const int lane = tid & 31;
    const int w = tid >> 5;                              // 0..15
    const int b = blockIdx.x;

    const uint32_t stageU =
        (uint32_t)__cvta_generic_to_shared(stage) + (uint32_t)(w * STQ) * 4u;
    const int rsel = lane >> 3;            // 0..3 : row sub-group
    const int csel = lane & 7;             // 16B chunk within 128B row

    if (w < 8) {
        // ======================= soft-DTW (warps 0..7, tid 0..255) ==========
        const int s0 = 32 * w + 2;                       // warp's first diagonal
        const int jj = tid + 1;                          // column (1-based)
        const int wp = (w == 0) ? 0 : (w - 1);

        for (int idx = tid; idx < 8 * 1312; idx += 256) bndR[idx] = BIGF;

        auto stageS = [&](int buf, int dgStart) {
#pragma unroll
            for (int r = 0; r < 4; r++) {
                int row = 4 * r + rsel;
                int dgr = dgStart + row;
                dgr = (dgr < 0) ? 0 : ((dgr > DGA - 1) ? DGA - 1 : dgr);
                uint32_t off = (uint32_t)((buf * KPH + row) * STROW + csel * 4) * 4u;
                cpAsync16(stageU + off,
                          g_cost + ((size_t)b * DGA + dgr) * NS + 32 * w + csel * 4);
            }
            cpCommit();
        };

        stageS(0, s0 + (0 - MLAG_S * w) * KPH);
        stageS(1, s0 + (1 - MLAG_S * w) * KPH);
        barNamed(1);                                     // bndR init visible

        float Rp = BIGF;
        float r3c = (tid == 0) ? 0.f : BIGF;

        int buf = 0;
        for (int p = 0; p < NPH_S; p++) {
            int bufN = buf + 2; if (bufN >= 3) bufN -= 3;
            stageS(bufN, s0 + (p + 2 - MLAG_S * w) * KPH);
            cpWait2();
            __syncwarp();
            const int prel = p - MLAG_S * w;
            if (prel >= 0 && prel <= 65) {
                const int stB = prel * KPH;
                const float* rowB = stage + w * STQ + buf * KPH * STROW + lane;
#pragma unroll
                for (int k = 0; k < KPH; k++) {
                    const int dg = s0 + stB + k;
                    float c = rowB[k * STROW];
                    float r2 = __shfl_up_sync(0xffffffffu, Rp, 1);
                    float bnd = bndR[wp * 1312 + dg - 1];          // broadcast LDS
                    r2 = (lane == 0) ? ((w == 0) ? BIGF : bnd) : r2;
                    float mn, md, mx;
                    sort3(Rp, r2, r3c, mn, md, mx);
                    float sv = 1.f + __expf((mn - md) * 10.f) + __expf((mn - mx) * 10.f);
                    const int i = dg - jj;
                    float Rn = (i >= 1 && i <= NT) ? (c + mn - GAMMA * __logf(sv)) : BIGF;
                    if (lane == 31) bndR[w * 1312 + dg] = Rn;
                    if (dg == NT + NS && tid == 255) g_loss[NB + b] = Rn;
                    r3c = r2;
                    Rp = Rn;
                }
            }
            buf++; if (buf >= 3) buf -= 3;
            barNamed(1);
        }
    } else {
        // ======================= CTC forward (warps 8..15) ===================
        const int ltid = tid - 256;                      // 0..255
        const int wc = w - 8;                            // 0..7
        const int wp = (wc == 0) ? 0 : (wc - 1);
        // thread owns states 2*ltid (even/blank-type), 2*ltid+1 (odd/label ltid);
        // ltid 255 also owns state 512.
        bool skip = false;
        if (ltid > 0) skip = (targets[b * NS + ltid] != targets[b * NS + ltid - 1]);
        const float* em = g_em + (size_t)b * NT * EMW;
        const int len = in_len[b];

        auto stageC = [&](int buf, int tStart) {
#pragma unroll
            for (int r = 0; r < 4; r++) {
                int row = 4 * r + rsel;
                int tr = tStart + row;
                tr = (tr < 0) ? 0 : ((tr > NT - 1) ? NT - 1 : tr);
                uint32_t off = (uint32_t)((buf * KPH + row) * STROW + csel * 4) * 4u;
                cpAsync16(stageU + off, em + (size_t)tr * EMW + 32 * wc + csel * 4);
            }
            if (lane < KPH) {                             // blank per row
                int tr = tStart + lane;
                tr = (tr < 0) ? 0 : ((tr > NT - 1) ? NT - 1 : tr);
                cpAsync4(stageU + (uint32_t)((buf * KPH + lane) * STROW + 32) * 4u,
                         em + (size_t)tr * EMW + 256);
            }
            cpCommit();
        };

        stageC(0, 1 + (0 - wc) * KPH);
        stageC(1, 1 + (1 - wc) * KPH);

        // t = 0 init: state0 = blank emission, state1 = label0 emission
        float A0 = NEGF, A1 = NEGF, A4 = NEGF;
        if (ltid == 0) { A0 = em[256]; A1 = em[0]; }
        if (lane == 31) ringT[wc * 64] = A1;              // slot t=0
        barNamed(2);

        int buf = 0;
        for (int p = 0; p < NPH_C; p++) {
            int bufN = buf + 2; if (bufN >= 3) bufN -= 3;
            stageC(bufN, 1 + (p + 2 - wc) * KPH);
            cpWait2();
            __syncwarp();
            const int tB = 1 + (p - wc) * KPH;
            if (p >= wc && tB < len) {
                const float* rowB = stage + w * STQ + buf * KPH * STROW;
#pragma unroll
                for (int k = 0; k < KPH; k++) {
                    const int t = tB + k;
                    float e = rowB[k * STROW + lane];
                    float eb = rowB[k * STROW + 32];
                    float pA1 = __shfl_up_sync(0xffffffffu, A1, 1);
                    float bnd = ringT[wp * 64 + ((t - 1) & 63)];   // broadcast LDS
                    pA1 = (lane == 0) ? ((wc == 0) ? NEGF : bnd) : pA1;
                    if (t < len) {                                 // uniform per group
                        // even state 2ltid: lse(A0, prevA1) + blank
                        float m0 = fmaxf(A0, pA1);
                        float q0 = m0 + __logf(1.f + __expf(fminf(A0, pA1) - m0)) + eb;
                        // odd state 2ltid+1: lse(A1, A0, skip?prevA1:NEG) + label
                        float av = skip ? pA1 : NEGF;
                        float mn, md, mx;
                        sort3(A1, A0, av, mn, md, mx);
                        float q1 = mx + __logf(1.f + __expf(mn - mx) + __expf(md - mx)) + e;
                        // state 512 (even): lse(A4, state511 old) + blank — wc7 only
                        if (wc == 7) {
                            float m4 = fmaxf(A4, A1);
                            float q4 = m4 + __logf(1.f + __expf(fminf(A4, A1) - m4)) + eb;
                            A4 = (lane == 31) ? q4 : A4;
                        }
                        if (lane == 31) ringT[wc * 64 + (t & 63)] = q1;
                        A0 = q0; A1 = q1;
                    }
                }
            }
            buf++; if (buf >= 3) buf -= 3;
            barNamed(2);
        }

        actc[2 * ltid + 0] = A0;
        actc[2 * ltid + 1] = A1;
        if (ltid == 255) actc[512] = A4;
        barNamed(2);
        if (ltid == 0) {
            int tl = tg_len[b];
            float aL = actc[2 * tl];
            float aP = actc[2 * tl - 1];
            float m = fmaxf(aL, aP);
            float ll = m + __logf(__expf(aL - m) + __expf(aP - m));
            g_loss[b] = -ll / (float)tl;
        }
    }
}

// ----------------------------------------------------------------------------
// Kernel 5: final reduction to scalar
// ----------------------------------------------------------------------------
__global__ void reduce_kernel(float* __restrict__ out) {
    const int tid = threadIdx.x;      // 128
    float v = g_loss[tid];
#pragma unroll
    for (int o = 16; o > 0; o >>= 1) v += __shfl_down_sync(0xffffffffu, v, o);
    __shared__ float ws[4];
    if ((tid & 31) == 0) ws[tid >> 5] = v;
    __syncthreads();
    if (tid == 0) out[0] = (ws[0] + ws[1] + ws[2] + ws[3]) * (1.f / (float)NB);
}

extern "C" void kernel_launch(void* const* d_in, const int* in_sizes, int n_in,
                              void* d_out, int out_size) {
    const float* lp  = (const float*)d_in[0];  // (B,T,V) f32
    const float* fm  = (const float*)d_in[1];  // (V,D)   f32
    const int*   tgt = (const int*)  d_in[2];  // (B,S)   i32
    const int*   il  = (const int*)  d_in[3];  // (B,)    i32
    const int*   tl  = (const int*)  d_in[4];  // (B,)    i32
    float* out = (float*)d_out;

    // dynamic smem: stage 16*1728 + bndR 8*1312 + ringT 8*64 + actc 513 floats
    const int dynSmem = (16 * STQ + 8 * 1312 + 8 * 64 + 513) * 4;   // 156,676 B
    cudaFuncSetAttribute(main_kernel, cudaFuncAttributeMaxDynamicSharedMemorySize, dynSmem);

    prep_kernel<<<512, 256>>>(lp, fm);
    em_kernel<<<1024, 256>>>(lp, tgt);
    cost_kernel<<<dim3(16, 64), 256>>>(fm, tgt);
    main_kernel<<<NB, 512, dynSmem>>>(tgt, il, tl);
    reduce_kernel<<<1, 128>>>(out);
}

// round 13
// speedup vs baseline: 1.0424x; 1.0424x over previous
#include <cuda_runtime.h>
#include <cstddef>
#include <cstdint>

#define NB 64
#define NT 1024
#define NV 256
#define NS 256
#define ND 24
#define NL 513          // 2*NS+1
#define DGA 1344        // allocated dg rows per batch
#define EMW 260         // em row: [0..255]=labels, [256]=blank, pad to 260
#define KPH 16          // steps per phase
#define MLAG_S 3        // sdtw inter-warp lag (phases): (m-1)*16 >= 31 -> m=3
#define NPH_S 87        // sdtw phases: 66 active + 3*7 lag
#define NPH_C 71        // ctc phases: 64 active + 7 lag
#define STROW 36        // staged row: 32 data floats (+blank at [32] for ctc), padded
#define STQ (3 * KPH * STROW)   // per-warp stage floats (3 buffers)
#define GAMMA 0.1f
#define NEGF (-1e10f)
#define BIGF (1e10f)

// Scratch (no allocation allowed)
__device__ float g_pred[NB * NT * ND];            // predicted features (B,T,D)
__device__ float g_cost[(size_t)NB * DGA * NS];   // cost, [b][dg][j], dg=i+j+2
__device__ float g_em[(size_t)NB * NT * EMW];     // emissions per label + blank
__device__ float g_loss[2 * NB];                  // [0..63] ctc, [64..127] sdtw

// mn <= md <= mx with pure min/max (no cancellation)
__device__ __forceinline__ void sort3(float a, float b, float c,
                                      float& mn, float& md, float& mx) {
    float t1 = fminf(a, b);
    float t2 = fmaxf(a, b);
    mn = fminf(t1, c);
    mx = fmaxf(t2, c);
    md = fmaxf(t1, fminf(t2, c));
}

__device__ __forceinline__ void cpAsync16(uint32_t dst, const void* src) {
    asm volatile("cp.async.cg.shared.global [%0], [%1], 16;" :: "r"(dst), "l"(src));
}
__device__ __forceinline__ void cpAsync4(uint32_t dst, const void* src) {
    asm volatile("cp.async.ca.shared.global [%0], [%1], 4;" :: "r"(dst), "l"(src));
}
__device__ __forceinline__ void cpCommit() {
    asm volatile("cp.async.commit_group;" ::: "memory");
}
__device__ __forceinline__ void cpWait2() {
    asm volatile("cp.async.wait_group 2;" ::: "memory");
}

// ----------------------------------------------------------------------------
// Kernel 1: pred = exp(log_probs) @ fm   (65536 x 256) @ (256 x 24)
// ----------------------------------------------------------------------------
__global__ __launch_bounds__(256) void prep_kernel(const float* __restrict__ lp,
                                                   const float* __restrict__ fm) {
    __shared__ float eS[64 * 129];
    __shared__ float fmS[64 * 25];

    const int tid = threadIdx.x;
    const int row0 = blockIdx.x * 128;
    const int rg = tid >> 3;
    const int dgrp = tid & 7;

    float acc[4][3];
#pragma unroll
    for (int i = 0; i < 4; i++)
#pragma unroll
        for (int j = 0; j < 3; j++) acc[i][j] = 0.f;

    for (int v0 = 0; v0 < NV; v0 += 64) {
        for (int idx = tid; idx < 64 * 24; idx += 256) {
            int v = idx / 24, d = idx - v * 24;
            fmS[v * 25 + d] = fm[(v0 + v) * ND + d];
        }
        for (int idx = tid; idx < 128 * 64; idx += 256) {
            int r = idx >> 6, v = idx & 63;
            eS[v * 129 + r] = __expf(lp[(size_t)(row0 + r) * NV + v0 + v]);
        }
        __syncthreads();

#pragma unroll 4
        for (int v = 0; v < 64; v++) {
            float e0 = eS[v * 129 + rg * 4 + 0];
            float e1 = eS[v * 129 + rg * 4 + 1];
            float e2 = eS[v * 129 + rg * 4 + 2];
            float e3 = eS[v * 129 + rg * 4 + 3];
            float f0 = fmS[v * 25 + dgrp * 3 + 0];
            float f1 = fmS[v * 25 + dgrp * 3 + 1];
            float f2 = fmS[v * 25 + dgrp * 3 + 2];
            acc[0][0] += e0 * f0; acc[0][1] += e0 * f1; acc[0][2] += e0 * f2;
            acc[1][0] += e1 * f0; acc[1][1] += e1 * f1; acc[1][2] += e1 * f2;
            acc[2][0] += e2 * f0; acc[2][1] += e2 * f1; acc[2][2] += e2 * f2;
            acc[3][0] += e3 * f0; acc[3][1] += e3 * f1; acc[3][2] += e3 * f2;
        }
        __syncthreads();
    }

#pragma unroll
    for (int i = 0; i < 4; i++)
#pragma unroll
        for (int j = 0; j < 3; j++)
            g_pred[(size_t)(row0 + rg * 4 + i) * ND + dgrp * 3 + j] = acc[i][j];
}

// ----------------------------------------------------------------------------
// Kernel 2: sdtw cost matrix, layout [b][dg][j], coalesced via diagonal rotation.
// ----------------------------------------------------------------------------
__global__ __launch_bounds__(256) void cost_kernel(const float* __restrict__ fm,
                                                   const int* __restrict__ targets) {
    __shared__ float predS[64 * 25];
    __shared__ float qS[256 * 25];
    __shared__ float pn[64];
    __shared__ float qn[256];
    __shared__ int qlab[256];

    const int tid = threadIdx.x;
    const int b = blockIdx.y;
    const int i0 = blockIdx.x * 64;

    qlab[tid] = targets[b * NS + tid];
    for (int idx = tid; idx < 64 * 24; idx += 256)
        predS[(idx / 24) * 25 + (idx % 24)] = g_pred[(size_t)(b * NT + i0) * ND + idx];
    __syncthreads();
    for (int idx = tid; idx < 256 * 24; idx += 256) {
        int c = idx / 24, d = idx - c * 24;
        qS[c * 25 + d] = fm[qlab[c] * ND + d];
    }
    __syncthreads();
    if (tid < 64) {
        float s = 0.f;
#pragma unroll
        for (int d = 0; d < ND; d++) { float x = predS[tid * 25 + d]; s += x * x; }
        pn[tid] = s;
    }
    {
        float s = 0.f;
#pragma unroll
        for (int d = 0; d < ND; d++) { float x = qS[tid * 25 + d]; s += x * x; }
        qn[tid] = s;
    }
    __syncthreads();

    const int w = tid >> 5;
    const int lane = tid & 31;
    const int j0 = w * 32;

    float p0[ND], p1[ND];
#pragma unroll
    for (int k = 0; k < ND; k++) {
        p0[k] = predS[lane * 25 + k];
        p1[k] = predS[(lane + 32) * 25 + k];
    }
    const float pn0 = pn[lane], pn1 = pn[lane + 32];
    const size_t cb = (size_t)b * DGA;
    const int D0 = i0 + j0 + 2;

#pragma unroll 4
    for (int c = 0; c < 32; c++) {
        int jc = j0 + ((c - lane) & 31);
        float dot0 = 0.f, dot1 = 0.f;
#pragma unroll
        for (int k = 0; k < ND; k++) {
            float q = qS[jc * 25 + k];
            dot0 += p0[k] * q;
            dot1 += p1[k] * q;
        }
        float qnj = qn[jc];
        int dg0 = D0 + c + ((lane > c) ? 32 : 0);
        g_cost[(cb + dg0) * NS + jc] = pn0 + qnj - 2.f * dot0;
        g_cost[(cb + dg0 + 32) * NS + jc] = pn1 + qnj - 2.f * dot1;
    }
}

// ----------------------------------------------------------------------------
// Kernel 3: emission table em[b][t][j] = lp[t][tgt[j]] (j<256); [256] = blank.
// ----------------------------------------------------------------------------
__global__ __launch_bounds__(256) void em_kernel(const float* __restrict__ lp,
                                                 const int* __restrict__ targets) {
    __shared__ float rowS[4][256];
    __shared__ int tgtS[256];

    const int tid = threadIdx.x;
    const int b = blockIdx.x >> 4;
    const int t0 = (blockIdx.x & 15) << 6;

    tgtS[tid] = targets[b * NS + tid];
    const float* lpb = lp + ((size_t)b * NT + t0) * NV;
    float* emb = g_em + ((size_t)b * NT + t0) * EMW;
    __syncthreads();

    for (int tt = 0; tt < 64; tt += 4) {
#pragma unroll
        for (int r = 0; r < 4; r++)
            rowS[r][tid] = lpb[(size_t)(tt + r) * NV + tid];
        __syncthreads();
#pragma unroll
        for (int r = 0; r < 4; r++)
            emb[(size_t)(tt + r) * EMW + tid] = rowS[r][tgtS[tid]];
        if (tid < 4) emb[(size_t)(tt + tid) * EMW + 256] = rowS[tid][0];
        __syncthreads();
    }
}

// ----------------------------------------------------------------------------
// Kernel 4 (fused DP, 8 warps/block = 2/SMSP; ALL smem reads preloaded into
// registers at phase start so the serial step body is shfl + reg math only):
//   blocks 0..63  -> soft-DTW : 1 col/thread, lag m=3
//   blocks 64..127-> CTC      : 2 states/thread, lag m=1
// ----------------------------------------------------------------------------
extern __shared__ float smf[];

__global__ __launch_bounds__(256) void main_kernel(const int* __restrict__ targets,
                                                   const int* __restrict__ in_len,
                                                   const int* __restrict__ tg_len) {
    float* stage = smf;                                  // [8][3][KPH][STROW]
    const int tid = threadIdx.x;                         // 0..255
    const int lane = tid & 31;
    const int w = tid >> 5;                              // 0..7
    const int bid = blockIdx.x;

    const uint32_t stageU =
        (uint32_t)__cvta_generic_to_shared(stage) + (uint32_t)(w * STQ) * 4u;
    const int rsel = lane >> 3;            // 0..3 : row sub-group
    const int csel = lane & 7;             // 16B chunk within 128B row

    if (bid < NB) {
        // ======================= soft-DTW =======================
        float* bndR = smf + 8 * STQ;                     // [8][1312]
        const int b = bid;
        const int s0 = 32 * w + 2;                       // warp's first diagonal
        const int jj = tid + 1;                          // column (1-based)
        const int wp = (w == 0) ? 0 : (w - 1);

        for (int idx = tid; idx < 8 * 1312; idx += 256) bndR[idx] = BIGF;

        auto stageS = [&](int buf, int dgStart) {
#pragma unroll
            for (int r = 0; r < 4; r++) {
                int row = 4 * r + rsel;
                int dgr = dgStart + row;
                dgr = (dgr < 0) ? 0 : ((dgr > DGA - 1) ? DGA - 1 : dgr);
                uint32_t off = (uint32_t)((buf * KPH + row) * STROW + csel * 4) * 4u;
                cpAsync16(stageU + off,
                          g_cost + ((size_t)b * DGA + dgr) * NS + 32 * w + csel * 4);
            }
            cpCommit();
        };

        stageS(0, s0 + (0 - MLAG_S * w) * KPH);
        stageS(1, s0 + (1 - MLAG_S * w) * KPH);
        __syncthreads();                                 // bndR init visible

        float Rp = BIGF;
        float r3c = (tid == 0) ? 0.f : BIGF;

        int buf = 0;
        for (int p = 0; p < NPH_S; p++) {
            int bufN = buf + 2; if (bufN >= 3) bufN -= 3;
            stageS(bufN, s0 + (p + 2 - MLAG_S * w) * KPH);
            cpWait2();
            __syncwarp();
            const int prel = p - MLAG_S * w;
            if (prel >= 0 && prel <= 65) {
                const int stB = prel * KPH;
                const float* rowB = stage + w * STQ + buf * KPH * STROW + lane;
                // ---- preload phase (off the serial chain) ----
                float cc[KPH], rb[KPH];
#pragma unroll
                for (int k = 0; k < KPH; k++) {
                    cc[k] = rowB[k * STROW];
                    rb[k] = bndR[wp * 1312 + s0 + stB - 1 + k];   // broadcast, lag-safe
                }
                // ---- serial steps: registers + shfl only ----
#pragma unroll
                for (int k = 0; k < KPH; k++) {
                    const int dg = s0 + stB + k;
                    float r2 = __shfl_up_sync(0xffffffffu, Rp, 1);
                    r2 = (lane == 0) ? ((w == 0) ? BIGF : rb[k]) : r2;
                    float mn, md, mx;
                    sort3(Rp, r2, r3c, mn, md, mx);
                    float sv = 1.f + __expf((mn - md) * 10.f) + __expf((mn - mx) * 10.f);
                    const int i = dg - jj;
                    float Rn = (i >= 1 && i <= NT) ? (cc[k] + mn - GAMMA * __logf(sv)) : BIGF;
                    if (lane == 31) bndR[w * 1312 + dg] = Rn;
                    if (dg == NT + NS && tid == 255) g_loss[NB + b] = Rn;
                    r3c = r2;
                    Rp = Rn;
                }
            }
            buf++; if (buf >= 3) buf -= 3;
            __syncthreads();
        }
    } else {
        // ======================= CTC forward =======================
        float* ringT = smf + 8 * STQ;                    // [8][64]
        float* actc = ringT + 8 * 64;                    // [513]
        const int b = bid - NB;
        const int wp = (w == 0) ? 0 : (w - 1);
        bool skip = false;
        if (tid > 0) skip = (targets[b * NS + tid] != targets[b * NS + tid - 1]);
        const float* em = g_em + (size_t)b * NT * EMW;
        const int len = in_len[b];

        auto stageC = [&](int buf, int tStart) {
#pragma unroll
            for (int r = 0; r < 4; r++) {
                int row = 4 * r + rsel;
                int tr = tStart + row;
                tr = (tr < 0) ? 0 : ((tr > NT - 1) ? NT - 1 : tr);
                uint32_t off = (uint32_t)((buf * KPH + row) * STROW + csel * 4) * 4u;
                cpAsync16(stageU + off, em + (size_t)tr * EMW + 32 * w + csel * 4);
            }
            if (lane < KPH) {                             // blank per row
                int tr = tStart + lane;
                tr = (tr < 0) ? 0 : ((tr > NT - 1) ? NT - 1 : tr);
                cpAsync4(stageU + (uint32_t)((buf * KPH + lane) * STROW + 32) * 4u,
                         em + (size_t)tr * EMW + 256);
            }
            cpCommit();
        };

        stageC(0, 1 + (0 - w) * KPH);
        stageC(1, 1 + (1 - w) * KPH);

        // t = 0 init: state0 = blank emission, state1 = label0 emission
        float A0 = NEGF, A1 = NEGF, A4 = NEGF;
        if (tid == 0) { A0 = em[256]; A1 = em[0]; }
        if (lane == 31) ringT[w * 64] = A1;               // slot t=0
        __syncthreads();

        int buf = 0;
        for (int p = 0; p < NPH_C; p++) {
            int bufN = buf + 2; if (bufN >= 3) bufN -= 3;
            stageC(bufN, 1 + (p + 2 - w) * KPH);
            cpWait2();
            __syncwarp();
            const int tB = 1 + (p - w) * KPH;
            if (p >= w && tB < len) {
                const float* rowB = stage + w * STQ + buf * KPH * STROW;
                // ---- preload phase (off the serial chain) ----
                float ee[KPH], bb[KPH], rr[KPH];
#pragma unroll
                for (int k = 0; k < KPH; k++) {
                    ee[k] = rowB[k * STROW + lane];
                    bb[k] = rowB[k * STROW + 32];
                    rr[k] = ringT[wp * 64 + ((tB - 1 + k) & 63)];   // broadcast, lag-safe
                }
                // ---- serial steps: registers + shfl only ----
#pragma unroll
                for (int k = 0; k < KPH; k++) {
                    const int t = tB + k;
                    float pA1 = __shfl_up_sync(0xffffffffu, A1, 1);
                    pA1 = (lane == 0) ? ((w == 0) ? NEGF : rr[k]) : pA1;
                    if (t < len) {                                 // uniform per block
                        float m0 = fmaxf(A0, pA1);
                        float q0 = m0 + __logf(1.f + __expf(fminf(A0, pA1) - m0)) + bb[k];
                        float av = skip ? pA1 : NEGF;
                        float mn, md, mx;
                        sort3(A1, A0, av, mn, md, mx);
                        float q1 = mx + __logf(1.f + __expf(mn - mx) + __expf(md - mx)) + ee[k];
                        if (w == 7) {
                            float m4 = fmaxf(A4, A1);
                            float q4 = m4 + __logf(1.f + __expf(fminf(A4, A1) - m4)) + bb[k];
                            A4 = (lane == 31) ? q4 : A4;
                        }
                        if (lane == 31) ringT[w * 64 + (t & 63)] = q1;
                        A0 = q0; A1 = q1;
                    }
                }
            }
            buf++; if (buf >= 3) buf -= 3;
            __syncthreads();
        }

        actc[2 * tid + 0] = A0;
        actc[2 * tid + 1] = A1;
        if (tid == 255) actc[512] = A4;
        __syncthreads();
        if (tid == 0) {
            int tl = tg_len[b];
            float aL = actc[2 * tl];
            float aP = actc[2 * tl - 1];
            float m = fmaxf(aL, aP);
            float ll = m + __logf(__expf(aL - m) + __expf(aP - m));
            g_loss[b] = -ll / (float)tl;
        }
    }
}

// ----------------------------------------------------------------------------
// Kernel 5: final reduction to scalar
// ----------------------------------------------------------------------------
__global__ void reduce_kernel(float* __restrict__ out) {
    const int tid = threadIdx.x;      // 128
    float v = g_loss[tid];
#pragma unroll
    for (int o = 16; o > 0; o >>= 1) v += __shfl_down_sync(0xffffffffu, v, o);
    __shared__ float ws[4];
    if ((tid & 31) == 0) ws[tid >> 5] = v;
    __syncthreads();
    if (tid == 0) out[0] = (ws[0] + ws[1] + ws[2] + ws[3]) * (1.f / (float)NB);
}

extern "C" void kernel_launch(void* const* d_in, const int* in_sizes, int n_in,
                              void* d_out, int out_size) {
    const float* lp  = (const float*)d_in[0];  // (B,T,V) f32
    const float* fm  = (const float*)d_in[1];  // (V,D)   f32
    const int*   tgt = (const int*)  d_in[2];  // (B,S)   i32
    const int*   il  = (const int*)  d_in[3];  // (B,)    i32
    const int*   tl  = (const int*)  d_in[4];  // (B,)    i32
    float* out = (float*)d_out;

    // dynamic smem: stage 8*STQ + bndR 8*1312 floats (ctc side smaller) = 97,280 B
    const int dynSmem = (8 * STQ + 8 * 1312) * 4;
    cudaFuncSetAttribute(main_kernel, cudaFuncAttributeMaxDynamicSharedMemorySize, dynSmem);

    prep_kernel<<<512, 256>>>(lp, fm);
    em_kernel<<<1024, 256>>>(lp, tgt);
    cost_kernel<<<dim3(16, 64), 256>>>(fm, tgt);
    main_kernel<<<2 * NB, 256, dynSmem>>>(tgt, il, tl);
    reduce_kernel<<<1, 128>>>(out);
}

// round 14
// speedup vs baseline: 1.0498x; 1.0071x over previous
#include <cuda_runtime.h>
#include <cstddef>
#include <cstdint>

#define NB 64
#define NT 1024
#define NV 256
#define NS 256
#define ND 24
#define NL 513          // 2*NS+1
#define DGA 1344        // allocated dg rows per batch
#define EMW 260         // em row: [0..255]=labels, [256]=blank, pad to 260
#define KPH 16          // steps per phase
#define MLAG_S 3        // sdtw inter-warp lag (phases): (m-1)*16 >= 31 -> m=3
#define NPH_S 87        // sdtw phases: 66 active + 3*7 lag
#define NPH_C 71        // ctc phases: 64 active + 7 lag
#define STROW 36        // staged row: 32 data floats (+blank at [32] for ctc), padded
#define STQ (3 * KPH * STROW)   // per-warp stage floats (3 buffers)
#define GAMMA 0.1f
#define NEGF (-1e10f)
#define BIGF (1e10f)

// Scratch (no allocation allowed)
__device__ float g_pred[NB * NT * ND];            // predicted features (B,T,D)
__device__ float g_cost[(size_t)NB * DGA * NS];   // cost, [b][dg][j], dg=i+j+2
__device__ float g_em[(size_t)NB * NT * EMW];     // emissions per label + blank
__device__ float g_loss[2 * NB];                  // [0..63] ctc, [64..127] sdtw

// mn <= md <= mx with pure min/max (no cancellation)
__device__ __forceinline__ void sort3(float a, float b, float c,
                                      float& mn, float& md, float& mx) {
    float t1 = fminf(a, b);
    float t2 = fmaxf(a, b);
    mn = fminf(t1, c);
    mx = fmaxf(t2, c);
    md = fmaxf(t1, fminf(t2, c));
}

__device__ __forceinline__ void cpAsync16(uint32_t dst, const void* src) {
    asm volatile("cp.async.cg.shared.global [%0], [%1], 16;" :: "r"(dst), "l"(src));
}
__device__ __forceinline__ void cpAsync4(uint32_t dst, const void* src) {
    asm volatile("cp.async.ca.shared.global [%0], [%1], 4;" :: "r"(dst), "l"(src));
}
__device__ __forceinline__ void cpCommit() {
    asm volatile("cp.async.commit_group;" ::: "memory");
}
__device__ __forceinline__ void cpWait2() {
    asm volatile("cp.async.wait_group 2;" ::: "memory");
}

// ----------------------------------------------------------------------------
// Kernel 1: pred = exp(log_probs) @ fm   (65536 x 256) @ (256 x 24)
// ----------------------------------------------------------------------------
__global__ __launch_bounds__(256) void prep_kernel(const float* __restrict__ lp,
                                                   const float* __restrict__ fm) {
    __shared__ float eS[64 * 129];
    __shared__ float fmS[64 * 25];

    const int tid = threadIdx.x;
    const int row0 = blockIdx.x * 128;
    const int rg = tid >> 3;
    const int dgrp = tid & 7;

    float acc[4][3];
#pragma unroll
    for (int i = 0; i < 4; i++)
#pragma unroll
        for (int j = 0; j < 3; j++) acc[i][j] = 0.f;

    for (int v0 = 0; v0 < NV; v0 += 64) {
        for (int idx = tid; idx < 64 * 24; idx += 256) {
            int v = idx / 24, d = idx - v * 24;
            fmS[v * 25 + d] = fm[(v0 + v) * ND + d];
        }
        for (int idx = tid; idx < 128 * 64; idx += 256) {
            int r = idx >> 6, v = idx & 63;
            eS[v * 129 + r] = __expf(lp[(size_t)(row0 + r) * NV + v0 + v]);
        }
        __syncthreads();

#pragma unroll 4
        for (int v = 0; v < 64; v++) {
            float e0 = eS[v * 129 + rg * 4 + 0];
            float e1 = eS[v * 129 + rg * 4 + 1];
            float e2 = eS[v * 129 + rg * 4 + 2];
            float e3 = eS[v * 129 + rg * 4 + 3];
            float f0 = fmS[v * 25 + dgrp * 3 + 0];
            float f1 = fmS[v * 25 + dgrp * 3 + 1];
            float f2 = fmS[v * 25 + dgrp * 3 + 2];
            acc[0][0] += e0 * f0; acc[0][1] += e0 * f1; acc[0][2] += e0 * f2;
            acc[1][0] += e1 * f0; acc[1][1] += e1 * f1; acc[1][2] += e1 * f2;
            acc[2][0] += e2 * f0; acc[2][1] += e2 * f1; acc[2][2] += e2 * f2;
            acc[3][0] += e3 * f0; acc[3][1] += e3 * f1; acc[3][2] += e3 * f2;
        }
        __syncthreads();
    }

#pragma unroll
    for (int i = 0; i < 4; i++)
#pragma unroll
        for (int j = 0; j < 3; j++)
            g_pred[(size_t)(row0 + rg * 4 + i) * ND + dgrp * 3 + j] = acc[i][j];
}

// ----------------------------------------------------------------------------
// Kernel 2: sdtw cost matrix, layout [b][dg][j], coalesced via diagonal rotation.
// ----------------------------------------------------------------------------
__global__ __launch_bounds__(256) void cost_kernel(const float* __restrict__ fm,
                                                   const int* __restrict__ targets) {
    __shared__ float predS[64 * 25];
    __shared__ float qS[256 * 25];
    __shared__ float pn[64];
    __shared__ float qn[256];
    __shared__ int qlab[256];

    const int tid = threadIdx.x;
    const int b = blockIdx.y;
    const int i0 = blockIdx.x * 64;

    qlab[tid] = targets[b * NS + tid];
    for (int idx = tid; idx < 64 * 24; idx += 256)
        predS[(idx / 24) * 25 + (idx % 24)] = g_pred[(size_t)(b * NT + i0) * ND + idx];
    __syncthreads();
    for (int idx = tid; idx < 256 * 24; idx += 256) {
        int c = idx / 24, d = idx - c * 24;
        qS[c * 25 + d] = fm[qlab[c] * ND + d];
    }
    __syncthreads();
    if (tid < 64) {
        float s = 0.f;
#pragma unroll
        for (int d = 0; d < ND; d++) { float x = predS[tid * 25 + d]; s += x * x; }
        pn[tid] = s;
    }
    {
        float s = 0.f;
#pragma unroll
        for (int d = 0; d < ND; d++) { float x = qS[tid * 25 + d]; s += x * x; }
        qn[tid] = s;
    }
    __syncthreads();

    const int w = tid >> 5;
    const int lane = tid & 31;
    const int j0 = w * 32;

    float p0[ND], p1[ND];
#pragma unroll
    for (int k = 0; k < ND; k++) {
        p0[k] = predS[lane * 25 + k];
        p1[k] = predS[(lane + 32) * 25 + k];
    }
    const float pn0 = pn[lane], pn1 = pn[lane + 32];
    const size_t cb = (size_t)b * DGA;
    const int D0 = i0 + j0 + 2;

#pragma unroll 4
    for (int c = 0; c < 32; c++) {
        int jc = j0 + ((c - lane) & 31);
        float dot0 = 0.f, dot1 = 0.f;
#pragma unroll
        for (int k = 0; k < ND; k++) {
            float q = qS[jc * 25 + k];
            dot0 += p0[k] * q;
            dot1 += p1[k] * q;
        }
        float qnj = qn[jc];
        int dg0 = D0 + c + ((lane > c) ? 32 : 0);
        g_cost[(cb + dg0) * NS + jc] = pn0 + qnj - 2.f * dot0;
        g_cost[(cb + dg0 + 32) * NS + jc] = pn1 + qnj - 2.f * dot1;
    }
}

// ----------------------------------------------------------------------------
// Kernel 3: emission table em[b][t][j] = lp[t][tgt[j]] (j<256); [256] = blank.
// ----------------------------------------------------------------------------
__global__ __launch_bounds__(256) void em_kernel(const float* __restrict__ lp,
                                                 const int* __restrict__ targets) {
    __shared__ float rowS[4][256];
    __shared__ int tgtS[256];

    const int tid = threadIdx.x;
    const int b = blockIdx.x >> 4;
    const int t0 = (blockIdx.x & 15) << 6;

    tgtS[tid] = targets[b * NS + tid];
    const float* lpb = lp + ((size_t)b * NT + t0) * NV;
    float* emb = g_em + ((size_t)b * NT + t0) * EMW;
    __syncthreads();

    for (int tt = 0; tt < 64; tt += 4) {
#pragma unroll
        for (int r = 0; r < 4; r++)
            rowS[r][tid] = lpb[(size_t)(tt + r) * NV + tid];
        __syncthreads();
#pragma unroll
        for (int r = 0; r < 4; r++)
            emb[(size_t)(tt + r) * EMW + tid] = rowS[r][tgtS[tid]];
        if (tid < 4) emb[(size_t)(tt + tid) * EMW + 256] = rowS[tid][0];
        __syncthreads();
    }
}

// ----------------------------------------------------------------------------
// Kernel 4 (fused DP, 8 warps/block = 2/SMSP; ALL smem reads preloaded into
// registers at phase start so the serial step body is shfl + reg math only):
//   blocks 0..63  -> soft-DTW : 1 col/thread, lag m=3
//   blocks 64..127-> CTC      : 2 states/thread, lag m=1
// ----------------------------------------------------------------------------
extern __shared__ float smf[];

__global__ __launch_bounds__(256) void main_kernel(const int* __restrict__ targets,
                                                   const int* __restrict__ in_len,
                                                   const int* __restrict__ tg_len) {
    float* stage = smf;                                  // [8][3][KPH][STROW]
    const int tid = threadIdx.x;                         // 0..255
    const int lane = tid & 31;
    const int w = tid >> 5;                              // 0..7
    const int bid = blockIdx.x;

    const uint32_t stageU =
        (uint32_t)__cvta_generic_to_shared(stage) + (uint32_t)(w * STQ) * 4u;
    const int rsel = lane >> 3;            // 0..3 : row sub-group
    const int csel = lane & 7;             // 16B chunk within 128B row

    if (bid < NB) {
        // ======================= soft-DTW =======================
        float* bndR = smf + 8 * STQ;                     // [8][1312]
        const int b = bid;
        const int s0 = 32 * w + 2;                       // warp's first diagonal
        const int jj = tid + 1;                          // column (1-based)
        const int wp = (w == 0) ? 0 : (w - 1);

        for (int idx = tid; idx < 8 * 1312; idx += 256) bndR[idx] = BIGF;

        auto stageS = [&](int buf, int dgStart) {
#pragma unroll
            for (int r = 0; r < 4; r++) {
                int row = 4 * r + rsel;
                int dgr = dgStart + row;
                dgr = (dgr < 0) ? 0 : ((dgr > DGA - 1) ? DGA - 1 : dgr);
                uint32_t off = (uint32_t)((buf * KPH + row) * STROW + csel * 4) * 4u;
                cpAsync16(stageU + off,
                          g_cost + ((size_t)b * DGA + dgr) * NS + 32 * w + csel * 4);
            }
            cpCommit();
        };

        stageS(0, s0 + (0 - MLAG_S * w) * KPH);
        stageS(1, s0 + (1 - MLAG_S * w) * KPH);
        __syncthreads();                                 // bndR init visible

        float Rp = BIGF;
        float r3c = (tid == 0) ? 0.f : BIGF;

        int buf = 0;
        for (int p = 0; p < NPH_S; p++) {
            int bufN = buf + 2; if (bufN >= 3) bufN -= 3;
            stageS(bufN, s0 + (p + 2 - MLAG_S * w) * KPH);
            cpWait2();
            __syncwarp();
            const int prel = p - MLAG_S * w;
            if (prel >= 0 && prel <= 65) {
                const int stB = prel * KPH;
                const float* rowB = stage + w * STQ + buf * KPH * STROW + lane;
                // ---- preload phase (off the serial chain) ----
                float cc[KPH], rb[KPH];
#pragma unroll
                for (int k = 0; k < KPH; k++) {
                    cc[k] = rowB[k * STROW];
                    rb[k] = bndR[wp * 1312 + s0 + stB - 1 + k];   // broadcast, lag-safe
                }
                // ---- serial steps: registers + shfl only ----
#pragma unroll
                for (int k = 0; k < KPH; k++) {
                    const int dg = s0 + stB + k;
                    float r2 = __shfl_up_sync(0xffffffffu, Rp, 1);
                    r2 = (lane == 0) ? ((w == 0) ? BIGF : rb[k]) : r2;
                    float mn, md, mx;
                    sort3(Rp, r2, r3c, mn, md, mx);
                    float sv = 1.f + __expf((mn - md) * 10.f) + __expf((mn - mx) * 10.f);
                    const int i = dg - jj;
                    float Rn = (i >= 1 && i <= NT) ? (cc[k] + mn - GAMMA * __logf(sv)) : BIGF;
                    if (lane == 31) bndR[w * 1312 + dg] = Rn;
                    if (dg == NT + NS && tid == 255) g_loss[NB + b] = Rn;
                    r3c = r2;
                    Rp = Rn;
                }
            }
            buf++; if (buf >= 3) buf -= 3;
            __syncthreads();
        }
    } else {
        // ======================= CTC forward =======================
        float* ringT = smf + 8 * STQ;                    // [8][64]
        float* actc = ringT + 8 * 64;                    // [513]
        const int b = bid - NB;
        const int wp = (w == 0) ? 0 : (w - 1);
        bool skip = false;
        if (tid > 0) skip = (targets[b * NS + tid] != targets[b * NS + tid - 1]);
        const float* em = g_em + (size_t)b * NT * EMW;
        const int len = in_len[b];

        auto stageC = [&](int buf, int tStart) {
#pragma unroll
            for (int r = 0; r < 4; r++) {
                int row = 4 * r + rsel;
                int tr = tStart + row;
                tr = (tr < 0) ? 0 : ((tr > NT - 1) ? NT - 1 : tr);
                uint32_t off = (uint32_t)((buf * KPH + row) * STROW + csel * 4) * 4u;
                cpAsync16(stageU + off, em + (size_t)tr * EMW + 32 * w + csel * 4);
            }
            if (lane < KPH) {                             // blank per row
                int tr = tStart + lane;
                tr = (tr < 0) ? 0 : ((tr > NT - 1) ? NT - 1 : tr);
                cpAsync4(stageU + (uint32_t)((buf * KPH + lane) * STROW + 32) * 4u,
                         em + (size_t)tr * EMW + 256);
            }
            cpCommit();
        };

        stageC(0, 1 + (0 - w) * KPH);
        stageC(1, 1 + (1 - w) * KPH);

        // t = 0 init: state0 = blank emission, state1 = label0 emission
        float A0 = NEGF, A1 = NEGF, A4 = NEGF;
        if (tid == 0) { A0 = em[256]; A1 = em[0]; }
        if (lane == 31) ringT[w * 64] = A1;               // slot t=0
        __syncthreads();

        int buf = 0;
        for (int p = 0; p < NPH_C; p++) {
            int bufN = buf + 2; if (bufN >= 3) bufN -= 3;
            stageC(bufN, 1 + (p + 2 - w) * KPH);
            cpWait2();
            __syncwarp();
            const int tB = 1 + (p - w) * KPH;
            if (p >= w && tB < len) {
                const float* rowB = stage + w * STQ + buf * KPH * STROW;
                // ---- preload phase (off the serial chain) ----
                float ee[KPH], bb[KPH], rr[KPH];
#pragma unroll
                for (int k = 0; k < KPH; k++) {
                    ee[k] = rowB[k * STROW + lane];
                    bb[k] = rowB[k * STROW + 32];
                    rr[k] = ringT[wp * 64 + ((tB - 1 + k) & 63)];   // broadcast, lag-safe
                }
                // ---- serial steps: registers + shfl only ----
#pragma unroll
                for (int k = 0; k < KPH; k++) {
                    const int t = tB + k;
                    float pA1 = __shfl_up_sync(0xffffffffu, A1, 1);
                    pA1 = (lane == 0) ? ((w == 0) ? NEGF : rr[k]) : pA1;
                    if (t < len) {                                 // uniform per block
                        float m0 = fmaxf(A0, pA1);
                        float q0 = m0 + __logf(1.f + __expf(fminf(A0, pA1) - m0)) + bb[k];
                        float av = skip ? pA1 : NEGF;
                        float mn, md, mx;
                        sort3(A1, A0, av, mn, md, mx);
                        float q1 = mx + __logf(1.f + __expf(mn - mx) + __expf(md - mx)) + ee[k];
                        if (w == 7) {
                            float m4 = fmaxf(A4, A1);
                            float q4 = m4 + __logf(1.f + __expf(fminf(A4, A1) - m4)) + bb[k];
                            A4 = (lane == 31) ? q4 : A4;
                        }
                        if (lane == 31) ringT[w * 64 + (t & 63)] = q1;
                        A0 = q0; A1 = q1;
                    }
                }
            }
            buf++; if (buf >= 3) buf -= 3;
            __syncthreads();
        }

        actc[2 * tid + 0] = A0;
        actc[2 * tid + 1] = A1;
        if (tid == 255) actc[512] = A4;
        __syncthreads();
        if (tid == 0) {
            int tl = tg_len[b];
            float aL = actc[2 * tl];
            float aP = actc[2 * tl - 1];
            float m = fmaxf(aL, aP);
            float ll = m + __logf(__expf(aL - m) + __expf(aP - m));
            g_loss[b] = -ll / (float)tl;
        }
    }
}

// ----------------------------------------------------------------------------
// Kernel 5: final reduction to scalar
// ----------------------------------------------------------------------------
__global__ void reduce_kernel(float* __restrict__ out) {
    const int tid = threadIdx.x;      // 128
    float v = g_loss[tid];
#pragma unroll
    for (int o = 16; o > 0; o >>= 1) v += __shfl_down_sync(0xffffffffu, v, o);
    __shared__ float ws[4];
    if ((tid & 31) == 0) ws[tid >> 5] = v;
    __syncthreads();
    if (tid == 0) out[0] = (ws[0] + ws[1] + ws[2] + ws[3]) * (1.f / (float)NB);
}

extern "C" void kernel_launch(void* const* d_in, const int* in_sizes, int n_in,
                              void* d_out, int out_size) {
    const float* lp  = (const float*)d_in[0];  // (B,T,V) f32
    const float* fm  = (const float*)d_in[1];  // (V,D)   f32
    const int*   tgt = (const int*)  d_in[2];  // (B,S)   i32
    const int*   il  = (const int*)  d_in[3];  // (B,)    i32
    const int*   tl  = (const int*)  d_in[4];  // (B,)    i32
    float* out = (float*)d_out;

    // dynamic smem: stage 8*STQ + bndR 8*1312 floats (ctc side smaller) = 97,280 B
    const int dynSmem = (8 * STQ + 8 * 1312) * 4;
    cudaFuncSetAttribute(main_kernel, cudaFuncAttributeMaxDynamicSharedMemorySize, dynSmem);

    prep_kernel<<<512, 256>>>(lp, fm);
    em_kernel<<<1024, 256>>>(lp, tgt);
    cost_kernel<<<dim3(16, 64), 256>>>(fm, tgt);
    main_kernel<<<2 * NB, 256, dynSmem>>>(tgt, il, tl);
    reduce_kernel<<<1, 128>>>(out);
}